// round 10
// baseline (speedup 1.0000x reference)
#include <cuda_runtime.h>

// PatchIoULoss — FINAL (converged at the harness bench floor, ~6.62us).
//
// Reference's anchor loops run exactly once (B=16<64, C=1<64). Per batch b
// over the top-left 64x64 patch of (16,1,1024,1024) f32 images:
//   iand_b = sum(pred*target), ior_b = sum(pred)+sum(target)-iand_b
//   out = sum_b (1 - iand_b/ior_b)
//
// Converged structure (R4->R8 lineage; R9 probe falsified narrower blocks):
//   - 16 blocks x 1024 threads; exactly one float4 pair per thread =>
//     single front-batched memory round trip (regs 18).
//   - reduce only (I, S=sumP+sumT): ior = S - I.
//   - level-1: 5 shuffle rounds; level-2: lanes 0-15 combine 2 partials +
//     4 shuffle rounds; partials packed as float2 (one STS.64 per leader).
//   - finalize: one atomicAdd(double) packing arrival count (integer part)
//     and sum(loss)/32 (fraction); the atomic return value identifies the
//     last arriver, which writes the scalar output. No fence, no re-read.

#define BATCH 16
#define WIMG  1024
#define NT    1024

__device__ double g_acc = 0.0;

__global__ void __launch_bounds__(NT, 1)
patch_iou_kernel(const float* __restrict__ pred,
                 const float* __restrict__ target,
                 float* __restrict__ out)
{
    const int b   = blockIdx.x;
    const int tid = threadIdx.x;

    const float4* __restrict__ p =
        reinterpret_cast<const float4*>(pred   + (size_t)b * WIMG * WIMG);
    const float4* __restrict__ t =
        reinterpret_cast<const float4*>(target + (size_t)b * WIMG * WIMG);

    // Patch = 64 rows x 16 float4/row, row stride 256 float4.
    const int idx = ((tid >> 4) << 8) | (tid & 15);
    const float4 pv = p[idx];
    const float4 tv = t[idx];

    float iand = pv.x * tv.x;
    iand = fmaf(pv.y, tv.y, iand);
    iand = fmaf(pv.z, tv.z, iand);
    iand = fmaf(pv.w, tv.w, iand);
    float s = ((pv.x + pv.y) + (pv.z + pv.w)) +
              ((tv.x + tv.y) + (tv.z + tv.w));   // sumP + sumT combined

    // Level-1: two independent shuffle chains (pipeline per round).
#pragma unroll
    for (int o = 16; o > 0; o >>= 1) {
        iand += __shfl_down_sync(0xffffffffu, iand, o);
        s    += __shfl_down_sync(0xffffffffu, s,    o);
    }

    __shared__ float2 s_part[32];   // (I, S) per warp, one STS.64 per leader
    const int w = tid >> 5, l = tid & 31;
    if (l == 0) s_part[w] = make_float2(iand, s);
    __syncthreads();

    // Level-2: lanes 0-15 combine two float2 partials, then 4 rounds.
    if (w == 0 && l < 16) {
        const float2 a = s_part[l];
        const float2 c = s_part[l + 16];
        float I = a.x + c.x;
        float S = a.y + c.y;
#pragma unroll
        for (int o = 8; o > 0; o >>= 1) {
            I += __shfl_down_sync(0x0000ffffu, I, o);
            S += __shfl_down_sync(0x0000ffffu, S, o);
        }
        if (l == 0) {
            const float loss = 1.0f - __fdividef(I, S - I);
            // loss in (0,1); sum of loss/32 over 16 blocks stays in (0,0.5),
            // so the integer part of g_acc is exactly the arrival count and
            // the atomic return value identifies the last arriver.
            const double term = (double)loss * (1.0 / 32.0) + 1.0;
            const double old  = atomicAdd(&g_acc, term);
            if (old > 14.75) {                    // 16th (last) arriver
                *out  = (float)((old + term - 16.0) * 32.0);
                g_acc = 0.0;                      // reset for next replay
            }
        }
    }
}

extern "C" void kernel_launch(void* const* d_in, const int* in_sizes, int n_in,
                              void* d_out, int out_size)
{
    const float* pred   = (const float*)d_in[0];
    const float* target = (const float*)d_in[1];
    float* out          = (float*)d_out;
    patch_iou_kernel<<<BATCH, NT>>>(pred, target, out);
}

// round 11
// speedup vs baseline: 1.0435x; 1.0435x over previous
#include <cuda_runtime.h>

// PatchIoULoss — FINAL (converged at the harness bench floor, ~6.6us).
// R10 ran this exact binary twice: 6.624 and 6.912us => +-0.29us harness
// noise band, larger than any remaining kernel-side lever. Closed.
//
// Reference's anchor loops run exactly once (B=16<64, C=1<64). Per batch b
// over the top-left 64x64 patch of (16,1,1024,1024) f32 images:
//   iand_b = sum(pred*target), ior_b = sum(pred)+sum(target)-iand_b
//   out = sum_b (1 - iand_b/ior_b)
//
// Converged structure (R4->R8 lineage; R9 falsified narrower blocks, R2
// falsified wider grids, R3 falsified multi-load threads):
//   - 16 blocks x 1024 threads; exactly one float4 pair per thread =>
//     single front-batched memory round trip (regs 18).
//   - reduce only (I, S=sumP+sumT): ior = S - I.
//   - level-1: 5 shuffle rounds; level-2: lanes 0-15 combine 2 partials +
//     4 shuffle rounds; partials packed as float2 (one STS.64 per leader).
//   - finalize: one atomicAdd(double) packing arrival count (integer part)
//     and sum(loss)/32 (fraction); the atomic return value identifies the
//     last arriver, which writes the scalar output. No fence, no re-read.

#define BATCH 16
#define WIMG  1024
#define NT    1024

__device__ double g_acc = 0.0;

__global__ void __launch_bounds__(NT, 1)
patch_iou_kernel(const float* __restrict__ pred,
                 const float* __restrict__ target,
                 float* __restrict__ out)
{
    const int b   = blockIdx.x;
    const int tid = threadIdx.x;

    const float4* __restrict__ p =
        reinterpret_cast<const float4*>(pred   + (size_t)b * WIMG * WIMG);
    const float4* __restrict__ t =
        reinterpret_cast<const float4*>(target + (size_t)b * WIMG * WIMG);

    // Patch = 64 rows x 16 float4/row, row stride 256 float4.
    const int idx = ((tid >> 4) << 8) | (tid & 15);
    const float4 pv = p[idx];
    const float4 tv = t[idx];

    float iand = pv.x * tv.x;
    iand = fmaf(pv.y, tv.y, iand);
    iand = fmaf(pv.z, tv.z, iand);
    iand = fmaf(pv.w, tv.w, iand);
    float s = ((pv.x + pv.y) + (pv.z + pv.w)) +
              ((tv.x + tv.y) + (tv.z + tv.w));   // sumP + sumT combined

    // Level-1: two independent shuffle chains (pipeline per round).
#pragma unroll
    for (int o = 16; o > 0; o >>= 1) {
        iand += __shfl_down_sync(0xffffffffu, iand, o);
        s    += __shfl_down_sync(0xffffffffu, s,    o);
    }

    __shared__ float2 s_part[32];   // (I, S) per warp, one STS.64 per leader
    const int w = tid >> 5, l = tid & 31;
    if (l == 0) s_part[w] = make_float2(iand, s);
    __syncthreads();

    // Level-2: lanes 0-15 combine two float2 partials, then 4 rounds.
    if (w == 0 && l < 16) {
        const float2 a = s_part[l];
        const float2 c = s_part[l + 16];
        float I = a.x + c.x;
        float S = a.y + c.y;
#pragma unroll
        for (int o = 8; o > 0; o >>= 1) {
            I += __shfl_down_sync(0x0000ffffu, I, o);
            S += __shfl_down_sync(0x0000ffffu, S, o);
        }
        if (l == 0) {
            const float loss = 1.0f - __fdividef(I, S - I);
            // loss in (0,1); sum of loss/32 over 16 blocks stays in (0,0.5),
            // so the integer part of g_acc is exactly the arrival count and
            // the atomic return value identifies the last arriver.
            const double term = (double)loss * (1.0 / 32.0) + 1.0;
            const double old  = atomicAdd(&g_acc, term);
            if (old > 14.75) {                    // 16th (last) arriver
                *out  = (float)((old + term - 16.0) * 32.0);
                g_acc = 0.0;                      // reset for next replay
            }
        }
    }
}

extern "C" void kernel_launch(void* const* d_in, const int* in_sizes, int n_in,
                              void* d_out, int out_size)
{
    const float* pred   = (const float*)d_in[0];
    const float* target = (const float*)d_in[1];
    float* out          = (float*)d_out;
    patch_iou_kernel<<<BATCH, NT>>>(pred, target, out);
}